// round 16
// baseline (speedup 1.0000x reference)
#include <cuda_runtime.h>
#include <cuda_fp16.h>
#include <cstdint>
#include <math.h>

#define BB 2
#define LL 8192
#define DIMV 512
#define NH 8
#define HD 64
#define NEG_FILL -100000000.0f
#define ML (BB*LL)
#define QPRESCALE 0.180336880f   // SCALE * log2(e)
#define ONESH2 0x3C003C00u       // half2(1.0, 1.0)

// ---------------- scratch ----------------
__device__ __align__(16) __half g_qh[ML*DIMV];    // projected Q (half, pre-scaled by SCALE*log2e)
__device__ __align__(16) __half g_kh[ML*DIMV];
__device__ __align__(16) __half g_vh[ML*DIMV];
__device__ __align__(16) __half g_xq[ML*DIMV];
__device__ __align__(16) __half g_xk[ML*DIMV];
__device__ __align__(16) __half g_xv[ML*DIMV];
__device__ __align__(16) __half g_wq[DIMV*DIMV];
__device__ __align__(16) __half g_wk[DIMV*DIMV];
__device__ __align__(16) __half g_wv[DIMV*DIMV];
__device__ __align__(16) __half g_wo[DIMV*DIMV];
__device__ __align__(16) __half g_combh[ML*DIMV];
__device__ __align__(16) __half g_o0[ML*DIMV];
__device__ __align__(16) __half g_o1[ML*DIMV];
__device__ __align__(16) __half g_o2[ML*DIMV];
__device__ float g_l0[ML*NH];
__device__ float g_l1[ML*NH];
__device__ float g_l2[ML*NH];

// ---------------- helpers ----------------
__device__ __forceinline__ uint32_t packh2(float lo, float hi) {
    __half2 h = __floats2half2_rn(lo, hi);
    return *reinterpret_cast<uint32_t*>(&h);
}
__device__ __forceinline__ void mma16(float* c, const uint32_t* a, uint32_t b0, uint32_t b1) {
    asm volatile(
        "mma.sync.aligned.m16n8k16.row.col.f32.f16.f16.f32 "
        "{%0,%1,%2,%3}, {%4,%5,%6,%7}, {%8,%9}, {%0,%1,%2,%3};"
        : "+f"(c[0]), "+f"(c[1]), "+f"(c[2]), "+f"(c[3])
        : "r"(a[0]), "r"(a[1]), "r"(a[2]), "r"(a[3]), "r"(b0), "r"(b1));
}
__device__ __forceinline__ void ldsm_x4(uint32_t* r, uint32_t addr) {
    asm volatile("ldmatrix.sync.aligned.m8n8.x4.shared.b16 {%0,%1,%2,%3}, [%4];"
        : "=r"(r[0]), "=r"(r[1]), "=r"(r[2]), "=r"(r[3]) : "r"(addr));
}
__device__ __forceinline__ void ldsm_x4t(uint32_t* r, uint32_t addr) {
    asm volatile("ldmatrix.sync.aligned.m8n8.x4.trans.shared.b16 {%0,%1,%2,%3}, [%4];"
        : "=r"(r[0]), "=r"(r[1]), "=r"(r[2]), "=r"(r[3]) : "r"(addr));
}
__device__ __forceinline__ uint32_t smem_u32(const void* p) {
    uint32_t a;
    asm("{ .reg .u64 t; cvta.to.shared.u64 t, %1; cvt.u32.u64 %0, t; }" : "=r"(a) : "l"(p));
    return a;
}
__device__ __forceinline__ void cp16(uint32_t dst, const void* src) {
    asm volatile("cp.async.cg.shared.global [%0], [%1], 16;" :: "r"(dst), "l"(src));
}
#define CP_COMMIT() asm volatile("cp.async.commit_group;" ::: "memory")
#define CP_WAIT1()  asm volatile("cp.async.wait_group 1;" ::: "memory")
#define CP_WAIT0()  asm volatile("cp.async.wait_group 0;" ::: "memory")

__device__ __forceinline__ float ex2f(float x) {
    float r;
    asm("ex2.approx.f32 %0, %1;" : "=f"(r) : "f"(x));
    return r;
}

// =====================================================================
// fp32 -> fp16 conversion kernels
// =====================================================================
__global__ __launch_bounds__(256) void conv_in(const float* __restrict__ q,
                                               const float* __restrict__ k,
                                               const float* __restrict__ v) {
    const float* src = (blockIdx.y == 0) ? q : (blockIdx.y == 1) ? k : v;
    __half* dst = (blockIdx.y == 0) ? g_xq : (blockIdx.y == 1) ? g_xk : g_xv;
    int i = blockIdx.x * blockDim.x + threadIdx.x;
    if (i >= ML * DIMV / 4) return;
    float4 a = ((const float4*)src)[i];
    ((__half2*)dst)[2*i]   = __floats2half2_rn(a.x, a.y);
    ((__half2*)dst)[2*i+1] = __floats2half2_rn(a.z, a.w);
}
__global__ __launch_bounds__(256) void conv_w(const float* __restrict__ wq,
                                              const float* __restrict__ wk,
                                              const float* __restrict__ wv,
                                              const float* __restrict__ wo) {
    const float* src = (blockIdx.y == 0) ? wq : (blockIdx.y == 1) ? wk :
                       (blockIdx.y == 2) ? wv : wo;
    __half* dst = (blockIdx.y == 0) ? g_wq : (blockIdx.y == 1) ? g_wk :
                  (blockIdx.y == 2) ? g_wv : g_wo;
    int i = blockIdx.x * blockDim.x + threadIdx.x;
    if (i >= DIMV * DIMV / 4) return;
    float4 a = ((const float4*)src)[i];
    ((__half2*)dst)[2*i]   = __floats2half2_rn(a.x, a.y);
    ((__half2*)dst)[2*i+1] = __floats2half2_rn(a.z, a.w);
}

// =====================================================================
// Pure fp16 GEMM: C[16384,512] = A @ W^T (+bias).
// CTA 128x128, 256 thr / 8 warps, warp tile 64x32, BK=64, ldmatrix.
// =====================================================================
#define GSTH 72
#define GHBUF (2*128*GSTH)
#define G_SMEM_BYTES (2*GHBUF*2)       // 73728

template <bool OUT_HALF>
__device__ __forceinline__ void gemm_body(const __half* __restrict__ A,
                                          const __half* __restrict__ W,
                                          const float* __restrict__ bias,
                                          float* __restrict__ Cf,
                                          __half* __restrict__ Ch,
                                          float oscale,
                                          __half* smg) {
    uint32_t sb = smem_u32(smg);
    const int t = threadIdx.x, lane = t & 31, w = t >> 5;
    const int g = lane >> 2, tg = lane & 3;
    const int m0 = blockIdx.x * 128, n0 = blockIdx.y * 128;
    const int wm = (w >> 2) * 64, wn = (w & 3) * 32;

    const int aRow = lane & 15,                 aCh = (lane >> 4) * 8;
    const int wRow = (lane & 7) + ((lane >> 4) & 1) * 8, wCh = ((lane >> 3) & 1) * 8;

    float c[4][4][4];
    #pragma unroll
    for (int i = 0; i < 4; i++)
        #pragma unroll
        for (int j = 0; j < 4; j++)
            #pragma unroll
            for (int q = 0; q < 4; q++) c[i][j][q] = 0.f;

    auto fill = [&](int ck, int buf) {
        #pragma unroll
        for (int r = 0; r < 4; r++) {
            int idx = t + r * 256;
            int row = idx >> 3, c8 = idx & 7;
            uint32_t dA = sb + (uint32_t)(buf * GHBUF + row * GSTH + c8 * 8) * 2u;
            cp16(dA, A + (size_t)(m0 + row) * 512 + ck * 64 + c8 * 8);
            uint32_t dW = sb + (uint32_t)(buf * GHBUF + 128 * GSTH + row * GSTH + c8 * 8) * 2u;
            cp16(dW, W + (size_t)(n0 + row) * 512 + ck * 64 + c8 * 8);
        }
        CP_COMMIT();
    };

    fill(0, 0);
    fill(1, 1);

    for (int ck = 0; ck < 8; ck++) {
        if (ck < 7) CP_WAIT1(); else CP_WAIT0();
        __syncthreads();
        uint32_t abase = sb + (uint32_t)((ck & 1) * GHBUF) * 2u;
        uint32_t wbase = abase + (uint32_t)(128 * GSTH) * 2u;
        #pragma unroll
        for (int ks = 0; ks < 4; ks++) {
            uint32_t af[4][4], bf[8];
            #pragma unroll
            for (int mt = 0; mt < 4; mt++)
                ldsm_x4(af[mt], abase +
                    (uint32_t)((wm + mt*16 + aRow) * GSTH + ks*16 + aCh) * 2u);
            ldsm_x4(bf,     wbase + (uint32_t)((wn + wRow)      * GSTH + ks*16 + wCh) * 2u);
            ldsm_x4(bf + 4, wbase + (uint32_t)((wn + 16 + wRow) * GSTH + ks*16 + wCh) * 2u);
            #pragma unroll
            for (int mt = 0; mt < 4; mt++)
                #pragma unroll
                for (int nt = 0; nt < 4; nt++)
                    mma16(c[mt][nt], af[mt], bf[nt*2], bf[nt*2+1]);
        }
        __syncthreads();
        if (ck + 2 < 8) fill(ck + 2, ck & 1);
    }

    #pragma unroll
    for (int mt = 0; mt < 4; mt++) {
        int row0 = m0 + wm + mt * 16 + g;
        #pragma unroll
        for (int nt = 0; nt < 4; nt++) {
            int col = n0 + wn + nt * 8 + 2 * tg;
            if (OUT_HALF) {
                *(__half2*)(Ch + (size_t)row0 * 512 + col) =
                    __floats2half2_rn(c[mt][nt][0] * oscale, c[mt][nt][1] * oscale);
                *(__half2*)(Ch + (size_t)(row0 + 8) * 512 + col) =
                    __floats2half2_rn(c[mt][nt][2] * oscale, c[mt][nt][3] * oscale);
            } else {
                float b0 = 0.f, b1 = 0.f;
                if (bias) { b0 = bias[col]; b1 = bias[col + 1]; }
                *(float2*)(Cf + (size_t)row0 * 512 + col) =
                    make_float2(c[mt][nt][0] + b0, c[mt][nt][1] + b1);
                *(float2*)(Cf + (size_t)(row0 + 8) * 512 + col) =
                    make_float2(c[mt][nt][2] + b0, c[mt][nt][3] + b1);
            }
        }
    }
}

__global__ __launch_bounds__(256, 2) void gemm_proj() {
    extern __shared__ __half smg[];
    const __half* A; const __half* W; __half* C; float sc;
    if (blockIdx.z == 0)      { A = g_xq; W = g_wq; C = g_qh; sc = QPRESCALE; }
    else if (blockIdx.z == 1) { A = g_xk; W = g_wk; C = g_kh; sc = 1.0f; }
    else                      { A = g_xv; W = g_wv; C = g_vh; sc = 1.0f; }
    gemm_body<true>(A, W, nullptr, nullptr, C, sc, smg);
}

__global__ __launch_bounds__(256, 2) void gemm_out(const float* __restrict__ bo,
                                                   float* __restrict__ out) {
    extern __shared__ __half smg[];
    gemm_body<false>(g_combh, g_wo, bo, out, nullptr, 1.0f, smg);
}

// =====================================================================
// fp16-mma flash attention — pipelined S/PV, 3-stage KV ring,
// 128-thread CTAs (4 warps), 2 CTAs co-resident per SM.
// CTA = 128 q rows of one (branch,b,seg,h) block -> 1792 CTAs.
// smem: 3 x (K 64x72 + V 64x72) halves = 55296 B per CTA.
// =====================================================================
#define KSTH 72
#define ABUF (64*KSTH)
#define A_SMEM_BYTES (6*ABUF*2)        // 55296

__global__ __launch_bounds__(128, 2) void attn_mma() {
    extern __shared__ __half smh[];
    uint32_t sb = smem_u32(smh);
    const int t = threadIdx.x, lane = t & 31, w = t >> 5;
    const int g = lane >> 2, tg = lane & 3;

    int bid = blockIdx.x;
    int br, rem;
    if (bid < 1024)      { br = 0; rem = bid; }
    else if (bid < 1536) { br = 1; rem = bid - 1024; }
    else                 { br = 2; rem = bid - 1536; }
    int sl, dr, nseg;
    if (br == 0)      { sl = 1024; dr = 1; nseg = 8; }
    else if (br == 1) { sl = 2048; dr = 2; nseg = 4; }
    else              { sl = 4096; dr = 4; nseg = 2; }
    int qt = rem & 7; rem >>= 3;
    int h  = rem & 7; rem >>= 3;
    int seg = rem % nseg;
    int b   = rem / nseg;
    int off = h / (NH / dr);
    __half* og = (br == 0) ? g_o0 : (br == 1) ? g_o1 : g_o2;
    float*  lg = (br == 0) ? g_l0 : (br == 1) ? g_l1 : g_l2;
    const size_t baseBL = (size_t)b * LL;

    // ---- stage the CTA's 128 Q rows (first ring stage region) ----
    #pragma unroll
    for (int i = 0; i < 8; i++) {
        int idx = t + i * 128;
        int row = idx >> 3, c8 = idx & 7;
        int p = seg * sl + (qt * 128 + row) * dr + off;
        cp16(sb + (uint32_t)(row * KSTH + c8 * 8) * 2u,
             g_qh + (baseBL + p) * 512 + h * 64 + c8 * 8);
    }
    CP_COMMIT();
    CP_WAIT0();
    __syncthreads();

    // ---- Q a-frags via ldmatrix.x4 (warp rows w*32 .. w*32+31) ----
    uint32_t qa[2][4][4];
    {
        int rl = w * 32 + (lane & 15);
        int ch = (lane >> 4) * 8;
        #pragma unroll
        for (int mt = 0; mt < 2; mt++)
            #pragma unroll
            for (int ks = 0; ks < 4; ks++)
                ldsm_x4(qa[mt][ks],
                        sb + (uint32_t)((rl + mt*16) * KSTH + ks*16 + ch) * 2u);
    }
    __syncthreads();

    auto fill = [&](int kt, int buf) {
        #pragma unroll
        for (int i = 0; i < 4; i++) {
            int idx = t + i * 128;
            int row = idx >> 3, c8 = idx & 7;
            int p = seg * sl + (kt * 64 + row) * dr + off;
            size_t gidx = (baseBL + p) * 512 + h * 64 + c8 * 8;
            uint32_t dK = sb + (uint32_t)(buf * 2 * ABUF + row * KSTH + c8 * 8) * 2u;
            cp16(dK, g_kh + gidx);
            cp16(dK + ABUF * 2u, g_vh + gidx);
        }
        CP_COMMIT();
    };

    float oc[2][8][4];
    #pragma unroll
    for (int mt = 0; mt < 2; mt++)
        #pragma unroll
        for (int db = 0; db < 8; db++)
            oc[mt][db][0] = oc[mt][db][1] = oc[mt][db][2] = oc[mt][db][3] = 0.f;
    float rsum[2][4];
    #pragma unroll
    for (int mt = 0; mt < 2; mt++)
        rsum[mt][0] = rsum[mt][1] = rsum[mt][2] = rsum[mt][3] = 0.f;

    const int kKeyOff = (lane & 7) + ((lane >> 4) & 1) * 8;
    const int kColOff = ((lane >> 3) & 1) * 8;
    const int vKeyOff = (lane & 7) + ((lane >> 3) & 1) * 8;
    const int vColOff = ((lane >> 4) & 1) * 8;

    auto do_S = [&](float sc[2][4][4], uint32_t kbase, int kh) {
        #pragma unroll
        for (int mt = 0; mt < 2; mt++)
            #pragma unroll
            for (int kb = 0; kb < 4; kb++)
                sc[mt][kb][0] = sc[mt][kb][1] = sc[mt][kb][2] = sc[mt][kb][3] = 0.f;
        #pragma unroll
        for (int ks = 0; ks < 4; ks++) {
            uint32_t bf[8];
            uint32_t ka = kbase +
                (uint32_t)((kh*32 + kKeyOff) * KSTH + kColOff + ks*16) * 2u;
            ldsm_x4(bf,     ka);
            ldsm_x4(bf + 4, ka + (uint32_t)(16 * KSTH) * 2u);
            #pragma unroll
            for (int mt = 0; mt < 2; mt++)
                #pragma unroll
                for (int kb = 0; kb < 4; kb++)
                    mma16(sc[mt][kb], qa[mt][ks], bf[kb*2], bf[kb*2+1]);
        }
    };

    auto do_exp = [&](float sc[2][4][4], uint32_t pf[2][2][4]) {
        #pragma unroll
        for (int mt = 0; mt < 2; mt++) {
            #pragma unroll
            for (int kbp = 0; kbp < 2; kbp++) {
                float a0 = ex2f(sc[mt][2*kbp][0]),   a1 = ex2f(sc[mt][2*kbp][1]);
                float a2 = ex2f(sc[mt][2*kbp][2]),   a3 = ex2f(sc[mt][2*kbp][3]);
                float b0 = ex2f(sc[mt][2*kbp+1][0]), b1 = ex2f(sc[mt][2*kbp+1][1]);
                float b2 = ex2f(sc[mt][2*kbp+1][2]), b3 = ex2f(sc[mt][2*kbp+1][3]);
                pf[mt][kbp][0] = packh2(a0, a1);
                pf[mt][kbp][1] = packh2(a2, a3);
                pf[mt][kbp][2] = packh2(b0, b1);
                pf[mt][kbp][3] = packh2(b2, b3);
                mma16(rsum[mt], pf[mt][kbp], ONESH2, ONESH2);
            }
        }
    };

    auto do_PV = [&](uint32_t pf[2][2][4], uint32_t vbase, int kh) {
        #pragma unroll
        for (int kbp = 0; kbp < 2; kbp++) {
            int key0 = kh*32 + kbp*16;
            #pragma unroll
            for (int dbp = 0; dbp < 4; dbp++) {
                uint32_t vb[4];
                ldsm_x4t(vb, vbase +
                    (uint32_t)((key0 + vKeyOff) * KSTH + dbp*16 + vColOff) * 2u);
                mma16(oc[0][dbp*2],   pf[0][kbp], vb[0], vb[1]);
                mma16(oc[0][dbp*2+1], pf[0][kbp], vb[2], vb[3]);
                mma16(oc[1][dbp*2],   pf[1][kbp], vb[0], vb[1]);
                mma16(oc[1][dbp*2+1], pf[1][kbp], vb[2], vb[3]);
            }
        }
    };

    fill(0, 0);
    fill(1, 1);

    float scA[2][4][4], scB[2][4][4];
    uint32_t pf[2][2][4];
    uint32_t vbase_prev = 0;

    for (int kt = 0; kt < 16; kt++) {
        if (kt < 15) CP_WAIT1(); else CP_WAIT0();
        __syncthreads();                           // fill(kt) visible to all
        uint32_t kbase = sb + (uint32_t)((kt % 3) * 2 * ABUF) * 2u;
        uint32_t vbase = kbase + (uint32_t)ABUF * 2u;

        do_S(scA, kbase, 0);                       // u = 2kt
        if (kt > 0) do_PV(pf, vbase_prev, 1);      // consume u = 2kt-1
        __syncthreads();                           // buffer kt-1 fully consumed
        if (kt < 14) fill(kt + 2, (kt + 2) % 3);
        do_exp(scA, pf);

        do_S(scB, kbase, 1);                       // u = 2kt+1
        do_PV(pf, vbase, 0);                       // consume u = 2kt
        do_exp(scB, pf);

        vbase_prev = vbase;
    }
    do_PV(pf, vbase_prev, 1);                      // final half

    // ---- epilogue ----
    #pragma unroll
    for (int mt = 0; mt < 2; mt++) {
        #pragma unroll
        for (int rs = 0; rs < 2; rs++) {
            float rsv = rsum[mt][rs*2];
            int qrow = qt * 128 + w * 32 + mt * 16 + g + rs * 8;
            int p = seg * sl + qrow * dr + off;
            float inv = 1.f / rsv;
            __half* op = og + (baseBL + p) * 512 + h * 64;
            #pragma unroll
            for (int db = 0; db < 8; db++) {
                *(__half2*)(op + db * 8 + 2 * tg) =
                    __floats2half2_rn(oc[mt][db][rs*2+0] * inv,
                                      oc[mt][db][rs*2+1] * inv);
            }
            if (tg == 0) {
                float lse = logf(rsv);
                if (lse == 0.0f) lse = NEG_FILL;
                lg[(baseBL + p) * NH + h] = lse;
            }
        }
    }
}

// =====================================================================
// Combine branches (half inputs, half output).
// =====================================================================
__global__ __launch_bounds__(256) void combine_kernel() {
    int idx4 = blockIdx.x * blockDim.x + threadIdx.x;
    if (idx4 >= ML * DIMV / 4) return;
    int col4 = idx4 & 127;
    int row  = idx4 >> 7;
    int h    = col4 >> 4;
    int p    = row & (LL - 1);
    int li   = row * NH + h;

    float l1 = g_l0[li];
    float l2 = ((p & 1) == (h >> 2)) ? g_l1[li] : NEG_FILL;
    float l3 = ((p & 3) == (h >> 1)) ? g_l2[li] : NEG_FILL;
    float mm = fmaxf(l1, fmaxf(l2, l3));
    float w1 = __expf(l1 - mm), w2 = __expf(l2 - mm), w3 = __expf(l3 - mm);
    float inv = 1.f / (w1 + w2 + w3);
    w1 *= inv; w2 *= inv; w3 *= inv;

    __half2 a0 = ((const __half2*)g_o0)[2*idx4], a1 = ((const __half2*)g_o0)[2*idx4+1];
    __half2 b0 = ((const __half2*)g_o1)[2*idx4], b1 = ((const __half2*)g_o1)[2*idx4+1];
    __half2 c0 = ((const __half2*)g_o2)[2*idx4], c1 = ((const __half2*)g_o2)[2*idx4+1];
    float2 af0 = __half22float2(a0), af1 = __half22float2(a1);
    float2 bf0 = __half22float2(b0), bf1 = __half22float2(b1);
    float2 cf0 = __half22float2(c0), cf1 = __half22float2(c1);

    float ox = w1*af0.x + w2*bf0.x + w3*cf0.x;
    float oy = w1*af0.y + w2*bf0.y + w3*cf0.y;
    float oz = w1*af1.x + w2*bf1.x + w3*cf1.x;
    float ow = w1*af1.y + w2*bf1.y + w3*cf1.y;
    ((__half2*)g_combh)[2*idx4]   = __floats2half2_rn(ox, oy);
    ((__half2*)g_combh)[2*idx4+1] = __floats2half2_rn(oz, ow);
}

// =====================================================================
extern "C" void kernel_launch(void* const* d_in, const int* in_sizes, int n_in,
                              void* d_out, int out_size) {
    (void)in_sizes; (void)n_in; (void)out_size;
    const float* query = (const float*)d_in[0];
    const float* key_  = (const float*)d_in[1];
    const float* value = (const float*)d_in[2];
    const float* Wq    = (const float*)d_in[3];
    const float* Wk    = (const float*)d_in[4];
    const float* Wv    = (const float*)d_in[5];
    const float* Wo    = (const float*)d_in[6];
    const float* bo    = (const float*)d_in[7];
    float* out = (float*)d_out;

    cudaFuncSetAttribute(gemm_proj, cudaFuncAttributeMaxDynamicSharedMemorySize, G_SMEM_BYTES);
    cudaFuncSetAttribute(gemm_out,  cudaFuncAttributeMaxDynamicSharedMemorySize, G_SMEM_BYTES);
    cudaFuncSetAttribute(attn_mma,  cudaFuncAttributeMaxDynamicSharedMemorySize, A_SMEM_BYTES);

    {
        dim3 gi((ML * DIMV / 4 + 255) / 256, 3);
        conv_in<<<gi, 256>>>(query, key_, value);
        dim3 gw((DIMV * DIMV / 4 + 255) / 256, 4);
        conv_w<<<gw, 256>>>(Wq, Wk, Wv, Wo);
    }

    dim3 gp(128, 4, 3);
    gemm_proj<<<gp, 256, G_SMEM_BYTES>>>();

    attn_mma<<<1792, 128, A_SMEM_BYTES>>>();

    combine_kernel<<<ML * DIMV / 4 / 256, 256>>>();

    dim3 go(128, 4);
    gemm_out<<<go, 256, G_SMEM_BYTES>>>(bo, out);
}

// round 17
// speedup vs baseline: 1.4165x; 1.4165x over previous
#include <cuda_runtime.h>
#include <cuda_fp16.h>
#include <cstdint>
#include <math.h>

#define BB 2
#define LL 8192
#define DIMV 512
#define NH 8
#define HD 64
#define NEG_FILL -100000000.0f
#define ML (BB*LL)
#define QPRESCALE 0.180336880f   // SCALE * log2(e)
#define ONESH2 0x3C003C00u       // half2(1.0, 1.0)

// ---------------- scratch ----------------
__device__ __align__(16) __half g_qh[ML*DIMV];    // projected Q (pre-scaled by SCALE*log2e)
__device__ __align__(16) __half g_kh[ML*DIMV];
__device__ __align__(16) __half g_vh[ML*DIMV];
__device__ __align__(16) __half g_wq[DIMV*DIMV];
__device__ __align__(16) __half g_wk[DIMV*DIMV];
__device__ __align__(16) __half g_wv[DIMV*DIMV];
__device__ __align__(16) __half g_wo[DIMV*DIMV];
__device__ __align__(16) __half g_o0[ML*DIMV];
__device__ __align__(16) __half g_o1[ML*DIMV];
__device__ __align__(16) __half g_o2[ML*DIMV];
__device__ float g_l0[ML*NH];
__device__ float g_l1[ML*NH];
__device__ float g_l2[ML*NH];

// ---------------- helpers ----------------
__device__ __forceinline__ uint32_t packh2(float lo, float hi) {
    __half2 h = __floats2half2_rn(lo, hi);
    return *reinterpret_cast<uint32_t*>(&h);
}
__device__ __forceinline__ void mma16(float* c, const uint32_t* a, uint32_t b0, uint32_t b1) {
    asm volatile(
        "mma.sync.aligned.m16n8k16.row.col.f32.f16.f16.f32 "
        "{%0,%1,%2,%3}, {%4,%5,%6,%7}, {%8,%9}, {%0,%1,%2,%3};"
        : "+f"(c[0]), "+f"(c[1]), "+f"(c[2]), "+f"(c[3])
        : "r"(a[0]), "r"(a[1]), "r"(a[2]), "r"(a[3]), "r"(b0), "r"(b1));
}
__device__ __forceinline__ void ldsm_x4(uint32_t* r, uint32_t addr) {
    asm volatile("ldmatrix.sync.aligned.m8n8.x4.shared.b16 {%0,%1,%2,%3}, [%4];"
        : "=r"(r[0]), "=r"(r[1]), "=r"(r[2]), "=r"(r[3]) : "r"(addr));
}
__device__ __forceinline__ void ldsm_x4t(uint32_t* r, uint32_t addr) {
    asm volatile("ldmatrix.sync.aligned.m8n8.x4.trans.shared.b16 {%0,%1,%2,%3}, [%4];"
        : "=r"(r[0]), "=r"(r[1]), "=r"(r[2]), "=r"(r[3]) : "r"(addr));
}
__device__ __forceinline__ uint32_t smem_u32(const void* p) {
    uint32_t a;
    asm("{ .reg .u64 t; cvta.to.shared.u64 t, %1; cvt.u32.u64 %0, t; }" : "=r"(a) : "l"(p));
    return a;
}
__device__ __forceinline__ void cp16(uint32_t dst, const void* src) {
    asm volatile("cp.async.cg.shared.global [%0], [%1], 16;" :: "r"(dst), "l"(src));
}
#define CP_COMMIT() asm volatile("cp.async.commit_group;" ::: "memory")
#define CP_WAIT1()  asm volatile("cp.async.wait_group 1;" ::: "memory")
#define CP_WAIT0()  asm volatile("cp.async.wait_group 0;" ::: "memory")

__device__ __forceinline__ float ex2f(float x) {
    float r;
    asm("ex2.approx.f32 %0, %1;" : "=f"(r) : "f"(x));
    return r;
}
// weighted 3-way combine of packed half2
__device__ __forceinline__ uint32_t comb2(uint32_t a, uint32_t b, uint32_t c,
                                          float w1, float w2, float w3) {
    float2 fa = __half22float2(*reinterpret_cast<__half2*>(&a));
    float2 fb = __half22float2(*reinterpret_cast<__half2*>(&b));
    float2 fc = __half22float2(*reinterpret_cast<__half2*>(&c));
    return packh2(w1*fa.x + w2*fb.x + w3*fc.x,
                  w1*fa.y + w2*fb.y + w3*fc.y);
}

// =====================================================================
// weight fp32 -> fp16 conversion (once; weights are read 128x each)
// =====================================================================
__global__ __launch_bounds__(256) void conv_w(const float* __restrict__ wq,
                                              const float* __restrict__ wk,
                                              const float* __restrict__ wv,
                                              const float* __restrict__ wo) {
    const float* src = (blockIdx.y == 0) ? wq : (blockIdx.y == 1) ? wk :
                       (blockIdx.y == 2) ? wv : wo;
    __half* dst = (blockIdx.y == 0) ? g_wq : (blockIdx.y == 1) ? g_wk :
                  (blockIdx.y == 2) ? g_wv : g_wo;
    int i = blockIdx.x * blockDim.x + threadIdx.x;
    if (i >= DIMV * DIMV / 4) return;
    float4 a = ((const float4*)src)[i];
    ((__half2*)dst)[2*i]   = __floats2half2_rn(a.x, a.y);
    ((__half2*)dst)[2*i+1] = __floats2half2_rn(a.z, a.w);
}

// =====================================================================
// GEMM common: CTA 128x128, 256 thr / 8 warps, warp tile 64x32,
// BK=64, ldmatrix fragment loads, stride-72 half rows.
// smem layout per stage: A halves [128*GSTH], then W halves [128*GSTH].
// =====================================================================
#define GSTH 72
#define GHBUF (2*128*GSTH)
#define G_SMEM_BYTES (2*GHBUF*2)       // 73728

// ---- projection GEMM: A read as fp32 (conversion fused into fill) ----
__global__ __launch_bounds__(256, 2) void gemm_proj(const float* __restrict__ q,
                                                    const float* __restrict__ k,
                                                    const float* __restrict__ v) {
    extern __shared__ __half smg[];
    const float* A; const __half* W; __half* C; float oscale;
    if (blockIdx.z == 0)      { A = q; W = g_wq; C = g_qh; oscale = QPRESCALE; }
    else if (blockIdx.z == 1) { A = k; W = g_wk; C = g_kh; oscale = 1.0f; }
    else                      { A = v; W = g_wv; C = g_vh; oscale = 1.0f; }

    uint32_t sb = smem_u32(smg);
    const int t = threadIdx.x, lane = t & 31, w = t >> 5;
    const int g = lane >> 2, tg = lane & 3;
    const int m0 = blockIdx.x * 128, n0 = blockIdx.y * 128;
    const int wm = (w >> 2) * 64, wn = (w & 3) * 32;

    const int aRow = lane & 15,                 aCh = (lane >> 4) * 8;
    const int wRow = (lane & 7) + ((lane >> 4) & 1) * 8, wCh = ((lane >> 3) & 1) * 8;

    float c[4][4][4];
    #pragma unroll
    for (int i = 0; i < 4; i++)
        #pragma unroll
        for (int j = 0; j < 4; j++)
            #pragma unroll
            for (int qq = 0; qq < 4; qq++) c[i][j][qq] = 0.f;

    auto fillA = [&](int ck, int buf) {            // fp32 -> half, LDG+STS
        #pragma unroll
        for (int r = 0; r < 4; r++) {
            int idx = t + r * 256;
            int row = idx >> 3, c8 = idx & 7;
            const float4* src = (const float4*)(A + (size_t)(m0 + row) * 512 + ck * 64 + c8 * 8);
            float4 f0 = src[0], f1 = src[1];
            uint4 hv = make_uint4(packh2(f0.x, f0.y), packh2(f0.z, f0.w),
                                  packh2(f1.x, f1.y), packh2(f1.z, f1.w));
            *(uint4*)((char*)smg + (size_t)(buf * GHBUF + row * GSTH + c8 * 8) * 2) = hv;
        }
    };
    auto fillW = [&](int ck, int buf) {            // half, cp.async
        #pragma unroll
        for (int r = 0; r < 4; r++) {
            int idx = t + r * 256;
            int row = idx >> 3, c8 = idx & 7;
            uint32_t dW = sb + (uint32_t)(buf * GHBUF + 128 * GSTH + row * GSTH + c8 * 8) * 2u;
            cp16(dW, W + (size_t)(n0 + row) * 512 + ck * 64 + c8 * 8);
        }
        CP_COMMIT();
    };

    fillA(0, 0); fillW(0, 0);
    fillA(1, 1); fillW(1, 1);

    for (int ck = 0; ck < 8; ck++) {
        if (ck < 7) CP_WAIT1(); else CP_WAIT0();
        __syncthreads();
        uint32_t abase = sb + (uint32_t)((ck & 1) * GHBUF) * 2u;
        uint32_t wbase = abase + (uint32_t)(128 * GSTH) * 2u;
        #pragma unroll
        for (int ks = 0; ks < 4; ks++) {
            uint32_t af[4][4], bf[8];
            #pragma unroll
            for (int mt = 0; mt < 4; mt++)
                ldsm_x4(af[mt], abase +
                    (uint32_t)((wm + mt*16 + aRow) * GSTH + ks*16 + aCh) * 2u);
            ldsm_x4(bf,     wbase + (uint32_t)((wn + wRow)      * GSTH + ks*16 + wCh) * 2u);
            ldsm_x4(bf + 4, wbase + (uint32_t)((wn + 16 + wRow) * GSTH + ks*16 + wCh) * 2u);
            #pragma unroll
            for (int mt = 0; mt < 4; mt++)
                #pragma unroll
                for (int nt = 0; nt < 4; nt++)
                    mma16(c[mt][nt], af[mt], bf[nt*2], bf[nt*2+1]);
        }
        __syncthreads();
        if (ck + 2 < 8) { fillA(ck + 2, ck & 1); fillW(ck + 2, ck & 1); }
    }

    #pragma unroll
    for (int mt = 0; mt < 4; mt++) {
        int row0 = m0 + wm + mt * 16 + g;
        #pragma unroll
        for (int nt = 0; nt < 4; nt++) {
            int col = n0 + wn + nt * 8 + 2 * tg;
            *(__half2*)(C + (size_t)row0 * 512 + col) =
                __floats2half2_rn(c[mt][nt][0] * oscale, c[mt][nt][1] * oscale);
            *(__half2*)(C + (size_t)(row0 + 8) * 512 + col) =
                __floats2half2_rn(c[mt][nt][2] * oscale, c[mt][nt][3] * oscale);
        }
    }
}

// ---- output GEMM: A = LSE-weighted combine of g_o0/1/2 (fused) ----
__global__ __launch_bounds__(256, 2) void gemm_out(const float* __restrict__ bo,
                                                   float* __restrict__ out) {
    extern __shared__ __half smg[];
    uint32_t sb = smem_u32(smg);
    const int t = threadIdx.x, lane = t & 31, w = t >> 5;
    const int g = lane >> 2, tg = lane & 3;
    const int m0 = blockIdx.x * 128, n0 = blockIdx.y * 128;
    const int wm = (w >> 2) * 64, wn = (w & 3) * 32;

    const int aRow = lane & 15,                 aCh = (lane >> 4) * 8;
    const int wRow = (lane & 7) + ((lane >> 4) & 1) * 8, wCh = ((lane >> 3) & 1) * 8;

    float c[4][4][4];
    #pragma unroll
    for (int i = 0; i < 4; i++)
        #pragma unroll
        for (int j = 0; j < 4; j++)
            #pragma unroll
            for (int qq = 0; qq < 4; qq++) c[i][j][qq] = 0.f;

    auto fillA = [&](int ck, int buf) {            // combine fused: chunk ck == head ck
        #pragma unroll
        for (int r = 0; r < 4; r++) {
            int idx = t + r * 256;
            int row = idx >> 3, c8 = idx & 7;
            int grow = m0 + row;
            int p = grow & (LL - 1);
            int h = ck;
            int li = grow * NH + h;
            float l1 = g_l0[li];
            float l2 = ((p & 1) == (h >> 2)) ? g_l1[li] : NEG_FILL;
            float l3 = ((p & 3) == (h >> 1)) ? g_l2[li] : NEG_FILL;
            float mm = fmaxf(l1, fmaxf(l2, l3));
            float w1 = __expf(l1 - mm), w2 = __expf(l2 - mm), w3 = __expf(l3 - mm);
            float inv = 1.f / (w1 + w2 + w3);
            w1 *= inv; w2 *= inv; w3 *= inv;
            size_t gidx = (size_t)grow * 512 + h * 64 + c8 * 8;
            uint4 o0 = *(const uint4*)(g_o0 + gidx);
            uint4 o1 = *(const uint4*)(g_o1 + gidx);
            uint4 o2 = *(const uint4*)(g_o2 + gidx);
            uint4 hv;
            hv.x = comb2(o0.x, o1.x, o2.x, w1, w2, w3);
            hv.y = comb2(o0.y, o1.y, o2.y, w1, w2, w3);
            hv.z = comb2(o0.z, o1.z, o2.z, w1, w2, w3);
            hv.w = comb2(o0.w, o1.w, o2.w, w1, w2, w3);
            *(uint4*)((char*)smg + (size_t)(buf * GHBUF + row * GSTH + c8 * 8) * 2) = hv;
        }
    };
    auto fillW = [&](int ck, int buf) {
        #pragma unroll
        for (int r = 0; r < 4; r++) {
            int idx = t + r * 256;
            int row = idx >> 3, c8 = idx & 7;
            uint32_t dW = sb + (uint32_t)(buf * GHBUF + 128 * GSTH + row * GSTH + c8 * 8) * 2u;
            cp16(dW, g_wo + (size_t)(n0 + row) * 512 + ck * 64 + c8 * 8);
        }
        CP_COMMIT();
    };

    fillA(0, 0); fillW(0, 0);
    fillA(1, 1); fillW(1, 1);

    for (int ck = 0; ck < 8; ck++) {
        if (ck < 7) CP_WAIT1(); else CP_WAIT0();
        __syncthreads();
        uint32_t abase = sb + (uint32_t)((ck & 1) * GHBUF) * 2u;
        uint32_t wbase = abase + (uint32_t)(128 * GSTH) * 2u;
        #pragma unroll
        for (int ks = 0; ks < 4; ks++) {
            uint32_t af[4][4], bf[8];
            #pragma unroll
            for (int mt = 0; mt < 4; mt++)
                ldsm_x4(af[mt], abase +
                    (uint32_t)((wm + mt*16 + aRow) * GSTH + ks*16 + aCh) * 2u);
            ldsm_x4(bf,     wbase + (uint32_t)((wn + wRow)      * GSTH + ks*16 + wCh) * 2u);
            ldsm_x4(bf + 4, wbase + (uint32_t)((wn + 16 + wRow) * GSTH + ks*16 + wCh) * 2u);
            #pragma unroll
            for (int mt = 0; mt < 4; mt++)
                #pragma unroll
                for (int nt = 0; nt < 4; nt++)
                    mma16(c[mt][nt], af[mt], bf[nt*2], bf[nt*2+1]);
        }
        __syncthreads();
        if (ck + 2 < 8) { fillA(ck + 2, ck & 1); fillW(ck + 2, ck & 1); }
    }

    #pragma unroll
    for (int mt = 0; mt < 4; mt++) {
        int row0 = m0 + wm + mt * 16 + g;
        #pragma unroll
        for (int nt = 0; nt < 4; nt++) {
            int col = n0 + wn + nt * 8 + 2 * tg;
            float b0 = bo[col], b1 = bo[col + 1];
            *(float2*)(out + (size_t)row0 * 512 + col) =
                make_float2(c[mt][nt][0] + b0, c[mt][nt][1] + b1);
            *(float2*)(out + (size_t)(row0 + 8) * 512 + col) =
                make_float2(c[mt][nt][2] + b0, c[mt][nt][3] + b1);
        }
    }
}

// =====================================================================
// fp16-mma flash attention — pipelined S/PV, 3-stage KV ring (R14 best).
// CTA = 256 q rows of one (branch,b,seg,h) block -> 896 CTAs, 256 thr.
// smem: 3 x (K 64x72 + V 64x72) halves = 55296 B.
// =====================================================================
#define KSTH 72
#define ABUF (64*KSTH)
#define A_SMEM_BYTES (6*ABUF*2)        // 55296

__global__ __launch_bounds__(256, 1) void attn_mma() {
    extern __shared__ __half smh[];
    uint32_t sb = smem_u32(smh);
    const int t = threadIdx.x, lane = t & 31, w = t >> 5;
    const int g = lane >> 2, tg = lane & 3;

    int bid = blockIdx.x;
    int br, rem;
    if (bid < 512)      { br = 0; rem = bid; }
    else if (bid < 768) { br = 1; rem = bid - 512; }
    else                { br = 2; rem = bid - 768; }
    int sl, dr, nseg;
    if (br == 0)      { sl = 1024; dr = 1; nseg = 8; }
    else if (br == 1) { sl = 2048; dr = 2; nseg = 4; }
    else              { sl = 4096; dr = 4; nseg = 2; }
    int qs = rem & 3; rem >>= 2;
    int h  = rem & 7; rem >>= 3;
    int seg = rem % nseg;
    int b   = rem / nseg;
    int off = h / (NH / dr);
    __half* og = (br == 0) ? g_o0 : (br == 1) ? g_o1 : g_o2;
    float*  lg = (br == 0) ? g_l0 : (br == 1) ? g_l1 : g_l2;
    const size_t baseBL = (size_t)b * LL;

    // ---- stage all 256 Q rows ----
    #pragma unroll
    for (int i = 0; i < 8; i++) {
        int idx = t + i * 256;
        int row = idx >> 3, c8 = idx & 7;
        int p = seg * sl + (qs * 256 + row) * dr + off;
        cp16(sb + (uint32_t)(row * KSTH + c8 * 8) * 2u,
             g_qh + (baseBL + p) * 512 + h * 64 + c8 * 8);
    }
    CP_COMMIT();
    CP_WAIT0();
    __syncthreads();

    // ---- Q a-frags via ldmatrix.x4 ----
    uint32_t qa[2][4][4];
    {
        int rl = w * 32 + (lane & 15);
        int ch = (lane >> 4) * 8;
        #pragma unroll
        for (int mt = 0; mt < 2; mt++)
            #pragma unroll
            for (int ks = 0; ks < 4; ks++)
                ldsm_x4(qa[mt][ks],
                        sb + (uint32_t)((rl + mt*16) * KSTH + ks*16 + ch) * 2u);
    }
    __syncthreads();

    auto fill = [&](int kt, int buf) {
        #pragma unroll
        for (int i = 0; i < 2; i++) {
            int idx = t + i * 256;
            int row = idx >> 3, c8 = idx & 7;
            int p = seg * sl + (kt * 64 + row) * dr + off;
            size_t gidx = (baseBL + p) * 512 + h * 64 + c8 * 8;
            uint32_t dK = sb + (uint32_t)(buf * 2 * ABUF + row * KSTH + c8 * 8) * 2u;
            cp16(dK, g_kh + gidx);
            cp16(dK + ABUF * 2u, g_vh + gidx);
        }
        CP_COMMIT();
    };

    float oc[2][8][4];
    #pragma unroll
    for (int mt = 0; mt < 2; mt++)
        #pragma unroll
        for (int db = 0; db < 8; db++)
            oc[mt][db][0] = oc[mt][db][1] = oc[mt][db][2] = oc[mt][db][3] = 0.f;
    float rsum[2][4];
    #pragma unroll
    for (int mt = 0; mt < 2; mt++)
        rsum[mt][0] = rsum[mt][1] = rsum[mt][2] = rsum[mt][3] = 0.f;

    const int kKeyOff = (lane & 7) + ((lane >> 4) & 1) * 8;
    const int kColOff = ((lane >> 3) & 1) * 8;
    const int vKeyOff = (lane & 7) + ((lane >> 3) & 1) * 8;
    const int vColOff = ((lane >> 4) & 1) * 8;

    auto do_S = [&](float sc[2][4][4], uint32_t kbase, int kh) {
        #pragma unroll
        for (int mt = 0; mt < 2; mt++)
            #pragma unroll
            for (int kb = 0; kb < 4; kb++)
                sc[mt][kb][0] = sc[mt][kb][1] = sc[mt][kb][2] = sc[mt][kb][3] = 0.f;
        #pragma unroll
        for (int ks = 0; ks < 4; ks++) {
            uint32_t bf[8];
            uint32_t ka = kbase +
                (uint32_t)((kh*32 + kKeyOff) * KSTH + kColOff + ks*16) * 2u;
            ldsm_x4(bf,     ka);
            ldsm_x4(bf + 4, ka + (uint32_t)(16 * KSTH) * 2u);
            #pragma unroll
            for (int mt = 0; mt < 2; mt++)
                #pragma unroll
                for (int kb = 0; kb < 4; kb++)
                    mma16(sc[mt][kb], qa[mt][ks], bf[kb*2], bf[kb*2+1]);
        }
    };

    auto do_exp = [&](float sc[2][4][4], uint32_t pf[2][2][4]) {
        #pragma unroll
        for (int mt = 0; mt < 2; mt++) {
            #pragma unroll
            for (int kbp = 0; kbp < 2; kbp++) {
                float a0 = ex2f(sc[mt][2*kbp][0]),   a1 = ex2f(sc[mt][2*kbp][1]);
                float a2 = ex2f(sc[mt][2*kbp][2]),   a3 = ex2f(sc[mt][2*kbp][3]);
                float b0 = ex2f(sc[mt][2*kbp+1][0]), b1 = ex2f(sc[mt][2*kbp+1][1]);
                float b2 = ex2f(sc[mt][2*kbp+1][2]), b3 = ex2f(sc[mt][2*kbp+1][3]);
                pf[mt][kbp][0] = packh2(a0, a1);
                pf[mt][kbp][1] = packh2(a2, a3);
                pf[mt][kbp][2] = packh2(b0, b1);
                pf[mt][kbp][3] = packh2(b2, b3);
                mma16(rsum[mt], pf[mt][kbp], ONESH2, ONESH2);
            }
        }
    };

    auto do_PV = [&](uint32_t pf[2][2][4], uint32_t vbase, int kh) {
        #pragma unroll
        for (int kbp = 0; kbp < 2; kbp++) {
            int key0 = kh*32 + kbp*16;
            #pragma unroll
            for (int dbp = 0; dbp < 4; dbp++) {
                uint32_t vb[4];
                ldsm_x4t(vb, vbase +
                    (uint32_t)((key0 + vKeyOff) * KSTH + dbp*16 + vColOff) * 2u);
                mma16(oc[0][dbp*2],   pf[0][kbp], vb[0], vb[1]);
                mma16(oc[0][dbp*2+1], pf[0][kbp], vb[2], vb[3]);
                mma16(oc[1][dbp*2],   pf[1][kbp], vb[0], vb[1]);
                mma16(oc[1][dbp*2+1], pf[1][kbp], vb[2], vb[3]);
            }
        }
    };

    fill(0, 0);
    fill(1, 1);

    float scA[2][4][4], scB[2][4][4];
    uint32_t pf[2][2][4];
    uint32_t vbase_prev = 0;

    for (int kt = 0; kt < 16; kt++) {
        if (kt < 15) CP_WAIT1(); else CP_WAIT0();
        __syncthreads();
        uint32_t kbase = sb + (uint32_t)((kt % 3) * 2 * ABUF) * 2u;
        uint32_t vbase = kbase + (uint32_t)ABUF * 2u;

        do_S(scA, kbase, 0);
        if (kt > 0) do_PV(pf, vbase_prev, 1);
        __syncthreads();
        if (kt < 14) fill(kt + 2, (kt + 2) % 3);
        do_exp(scA, pf);

        do_S(scB, kbase, 1);
        do_PV(pf, vbase, 0);
        do_exp(scB, pf);

        vbase_prev = vbase;
    }
    do_PV(pf, vbase_prev, 1);

    // ---- epilogue ----
    #pragma unroll
    for (int mt = 0; mt < 2; mt++) {
        #pragma unroll
        for (int rs = 0; rs < 2; rs++) {
            float rsv = rsum[mt][rs*2];
            int qrow = qs * 256 + w * 32 + mt * 16 + g + rs * 8;
            int p = seg * sl + qrow * dr + off;
            float inv = 1.f / rsv;
            __half* op = og + (baseBL + p) * 512 + h * 64;
            #pragma unroll
            for (int db = 0; db < 8; db++) {
                *(__half2*)(op + db * 8 + 2 * tg) =
                    __floats2half2_rn(oc[mt][db][rs*2+0] * inv,
                                      oc[mt][db][rs*2+1] * inv);
            }
            if (tg == 0) {
                float lse = logf(rsv);
                if (lse == 0.0f) lse = NEG_FILL;
                lg[(baseBL + p) * NH + h] = lse;
            }
        }
    }
}

// =====================================================================
extern "C" void kernel_launch(void* const* d_in, const int* in_sizes, int n_in,
                              void* d_out, int out_size) {
    (void)in_sizes; (void)n_in; (void)out_size;
    const float* query = (const float*)d_in[0];
    const float* key_  = (const float*)d_in[1];
    const float* value = (const float*)d_in[2];
    const float* Wq    = (const float*)d_in[3];
    const float* Wk    = (const float*)d_in[4];
    const float* Wv    = (const float*)d_in[5];
    const float* Wo    = (const float*)d_in[6];
    const float* bo    = (const float*)d_in[7];
    float* out = (float*)d_out;

    cudaFuncSetAttribute(gemm_proj, cudaFuncAttributeMaxDynamicSharedMemorySize, G_SMEM_BYTES);
    cudaFuncSetAttribute(gemm_out,  cudaFuncAttributeMaxDynamicSharedMemorySize, G_SMEM_BYTES);
    cudaFuncSetAttribute(attn_mma,  cudaFuncAttributeMaxDynamicSharedMemorySize, A_SMEM_BYTES);

    {
        dim3 gw((DIMV * DIMV / 4 + 255) / 256, 4);
        conv_w<<<gw, 256>>>(Wq, Wk, Wv, Wo);
    }

    dim3 gp(128, 4, 3);
    gemm_proj<<<gp, 256, G_SMEM_BYTES>>>(query, key_, value);

    attn_mma<<<896, 256, A_SMEM_BYTES>>>();

    dim3 go(128, 4);
    gemm_out<<<go, 256, G_SMEM_BYTES>>>(bo, out);
}